// round 15
// baseline (speedup 1.0000x reference)
#include <cuda_runtime.h>
#include <cstdint>
#include <math.h>

// RMAC: x [64, 2048, 16, 16] f32 -> out [64, 14*2048] f32, L2-normalized per batch.
// Regions: L1 1x(16x16), L2 4x(10x10, starts {0,4}), L3 9x(8x8, starts {0,3,6}).
// Single persistent kernel: pooling + per-tile sumsq partials, grid barrier,
// inverse-norm computation, grid barrier, in-place rescale.

#define B_TOT   64
#define C_TOT   2048
#define NREG    14
#define OUT_PER_B (NREG * C_TOT)        // 28672
#define OUT_F4_PER_B (OUT_PER_B / 4)    // 7168
#define OUT_F4_TOT (B_TOT * OUT_F4_PER_B) // 458752

#define CHB     16                      // channels per tile
#define TPB     128                     // threads per block
#define TILE_F4 (CHB * 64)              // 1024 float4 per tile (16 KiB)
#define TILE_W  (CHB * 256)             // 4096 floats
#define NTILES  (B_TOT * (C_TOT / CHB)) // 8192
#define GRID_MAIN 888                   // persistent: fully co-resident (6/SM x 148)
#define RSTRIDE 144                     // phase-3 smem stride (conflict-free combine)

__device__ float g_part[NTILES];        // per-tile sum of squares
__device__ float g_inv[B_TOT];          // per-batch 1/norm
__device__ unsigned g_cnt = 0;          // barrier arrivals (returns to 0 each pass)
__device__ unsigned g_gen = 0;          // barrier generation (monotonic across replays)

__device__ __forceinline__ void cp16(unsigned int s, const void* g) {
    asm volatile("cp.async.cg.shared.global [%0], [%1], 16;" :: "r"(s), "l"(g) : "memory");
}
__device__ __forceinline__ void cp_commit() {
    asm volatile("cp.async.commit_group;" ::: "memory");
}
__device__ __forceinline__ void cp_wait1() {
    asm volatile("cp.async.wait_group 1;" ::: "memory");
}
__device__ __forceinline__ void cp_wait0() {
    asm volatile("cp.async.wait_group 0;" ::: "memory");
}

// Grid-wide barrier. Safe only because all GRID_MAIN blocks are co-resident.
// Sense-reversing: last arriver resets cnt BEFORE bumping gen; spinners watch
// gen only. Deterministic across graph replays (cnt ends at 0, gen monotonic).
__device__ __forceinline__ void grid_barrier(int t) {
    __syncthreads();
    if (t == 0) {
        __threadfence();                                  // publish prior writes
        unsigned my = *((volatile unsigned*)&g_gen);      // before arriving: gen can't bump
        unsigned old = atomicAdd(&g_cnt, 1);
        if (old == GRID_MAIN - 1) {
            g_cnt = 0;                                    // all arrived; none reads cnt now
            __threadfence();
            atomicAdd(&g_gen, 1);                         // release
        } else {
            while (*((volatile unsigned*)&g_gen) == my) { }
            __threadfence();                              // acquire
        }
    }
    __syncthreads();
}

__global__ __launch_bounds__(TPB, 6) void rmac_fused_kernel(
    const float* __restrict__ x, float* __restrict__ out)
{
    __shared__ __align__(16) float sm[2 * TILE_W];   // 32 KiB, double buffer
    const int t = threadIdx.x;
    const unsigned int sbase = (unsigned int)__cvta_generic_to_shared(sm);

    // issue the 16 KiB tile load into buffer p (swizzled STS via cp.async)
    auto issue = [&](int tile, int p) {
        const float4* __restrict__ gv =
            reinterpret_cast<const float4*>(x) + (size_t)tile * TILE_F4;
        const unsigned int bb = sbase + (unsigned int)p * (TILE_W * 4);
        #pragma unroll
        for (int i = 0; i < TILE_F4 / TPB; i++) {    // 8 x cp.async per thread
            const int q  = i * TPB + t;
            const int ch = q >> 6;
            const int qw = q & 63;
            cp16(bb + (unsigned int)((ch * 64 + (qw ^ (ch & 7))) * 16), gv + q);
        }
    };

    const int t0 = blockIdx.x;
    if (t0 < NTILES) issue(t0, 0);
    cp_commit();
    if (t0 + GRID_MAIN < NTILES) issue(t0 + GRID_MAIN, 1);
    cp_commit();

    const int ch     = t & (CHB - 1);
    const int rchunk = t >> 4;
    const int sw     = ch & 7;

    int j = 0;
    for (int tile = t0; tile < NTILES; tile += GRID_MAIN, j++) {
        float* cur = sm + (j & 1) * TILE_W;
        const float4* __restrict__ cv = reinterpret_cast<const float4*>(cur) + ch * 64;

        cp_wait1();
        __syncthreads();

        // ---- pool 2 rows of one channel ----
        float acc[NREG];
        #pragma unroll
        for (int r = 0; r < NREG; r++) acc[r] = 0.0f;

        #pragma unroll
        for (int rr = 0; rr < 2; rr++) {
            const int h = rchunk * 2 + rr;
            float rowv[16];
            #pragma unroll
            for (int jj = 0; jj < 4; jj++) {
                const float4 v = cv[(h * 4 + jj) ^ sw];   // LDS.128, conflict-free
                rowv[jj*4+0] = v.x; rowv[jj*4+1] = v.y;
                rowv[jj*4+2] = v.z; rowv[jj*4+3] = v.w;
            }
            float pre[17];
            pre[0] = 0.0f;
            float p = 0.0f;
            #pragma unroll
            for (int q = 0; q < 16; q++) { p += rowv[q]; pre[q + 1] = p; }

            const float s16  = pre[16];
            const float c10a = pre[10];
            const float c10b = pre[14] - pre[4];
            const float c8a  = pre[8];
            const float c8b  = pre[11] - pre[3];
            const float c8c  = pre[14] - pre[6];

            acc[0] += s16;
            if (h < 10)           { acc[1]  += c10a; acc[2]  += c10b; }
            if (h >= 4 && h < 14) { acc[3]  += c10a; acc[4]  += c10b; }
            if (h < 8)            { acc[5]  += c8a;  acc[6]  += c8b;  acc[7]  += c8c; }
            if (h >= 3 && h < 11) { acc[8]  += c8a;  acc[9]  += c8b;  acc[10] += c8c; }
            if (h >= 6 && h < 14) { acc[11] += c8a;  acc[12] += c8b;  acc[13] += c8c; }
        }
        __syncthreads();

        // ---- combine 8 row-chunk partials per channel via smem (reuse cur) ----
        float* red = cur;                       // 14 * 144 = 2016 floats
        #pragma unroll
        for (int r = 0; r < NREG; r++) red[r * RSTRIDE + t] = acc[r];
        __syncthreads();

        const int b  = tile >> 7;               // 128 tiles per batch
        const int c0 = (tile & 127) * CHB;
        float* __restrict__ outb = out + (size_t)b * OUT_PER_B;
        float ss = 0.0f;
        #pragma unroll
        for (int idx = t; idx < NREG * CHB; idx += TPB) {   // 224 outputs
            const int r  = idx >> 4;
            const int cc = idx & 15;
            float v = 0.0f;
            #pragma unroll
            for (int k = 0; k < 8; k++) v += red[r * RSTRIDE + cc + 16 * k];
            const float inv_area = (r == 0) ? (1.0f / 256.0f)
                                  : (r < 5) ? (1.0f / 100.0f)
                                            : (1.0f / 64.0f);
            v *= inv_area;
            outb[r * C_TOT + c0 + cc] = v;
            ss += v * v;
        }

        // block-reduce ss -> g_part[tile] (plain store, no atomics)
        #pragma unroll
        for (int o = 16; o > 0; o >>= 1)
            ss += __shfl_down_sync(0xffffffffu, ss, o);
        float* wsum = cur + 2048;
        if ((t & 31) == 0) wsum[t >> 5] = ss;
        __syncthreads();
        if (t == 0) g_part[tile] = wsum[0] + wsum[1] + wsum[2] + wsum[3];
        __syncthreads();

        const int nt = tile + 2 * GRID_MAIN;
        if (nt < NTILES) issue(nt, j & 1);
        cp_commit();
    }

    // ---- drain async copies, then fuse the normalization ----
    cp_wait0();
    grid_barrier(t);       // all g_part / out writes visible chip-wide

    // Phase A: blocks 0..63 compute per-batch inverse norm (128 partials each)
    if (blockIdx.x < B_TOT) {
        float v = g_part[blockIdx.x * 128 + t];      // one partial per thread
        #pragma unroll
        for (int o = 16; o > 0; o >>= 1)
            v += __shfl_down_sync(0xffffffffu, v, o);
        if ((t & 31) == 0) sm[t >> 5] = v;
        __syncthreads();
        if (t == 0)
            g_inv[blockIdx.x] = 1.0f / fmaxf(sqrtf(sm[0] + sm[1] + sm[2] + sm[3]), 1e-12f);
    }
    grid_barrier(t);       // g_inv visible

    // Phase B: all blocks rescale out in place (mostly L2-resident)
    float4* __restrict__ o4 = reinterpret_cast<float4*>(out);
    for (int idx = blockIdx.x * TPB + t; idx < OUT_F4_TOT; idx += GRID_MAIN * TPB) {
        const float inv = g_inv[idx / OUT_F4_PER_B];
        float4 v = o4[idx];
        v.x *= inv; v.y *= inv; v.z *= inv; v.w *= inv;
        o4[idx] = v;
    }
}

extern "C" void kernel_launch(void* const* d_in, const int* in_sizes, int n_in,
                              void* d_out, int out_size) {
    (void)in_sizes; (void)n_in; (void)out_size;
    const float* x = (const float*)d_in[0];
    float* out = (float*)d_out;

    rmac_fused_kernel<<<GRID_MAIN, TPB>>>(x, out);
}